// round 7
// baseline (speedup 1.0000x reference)
#include <cuda_runtime.h>

// Shape fixed by the reference
#define B_     8
#define T_     4096
#define D_     1024
#define L_     16                  // timesteps per item (payload in registers)
#define NC_    (T_ / L_)           // 256 chunks per chain
#define SLICE_ 32                  // floats of D per chain (1 per lane)
#define NCHAIN (B_ * (D_ / SLICE_))// 256 independent chains
#define NITEM  (NCHAIN * NC_)      // 65536 warp-items
#define TPB    256                 // 8 warp-items per block
#define NBLK   (NITEM / 8)         // 8192 blocks
#define LB_W   8                   // lookback batch width

// Decoupled-lookback state (8 MB each -> L2-resident)
__device__ float    g_A[NITEM * SLICE_];  // item aggregate: prod(a) over chunk slice
__device__ float    g_U[NITEM * SLICE_];  // item aggregate: zero-carry scan tail
__device__ float    g_X[NITEM * SLICE_];  // item inclusive state
__device__ unsigned g_flag[NITEM];        // 0=invalid, 1=aggregate, 2=inclusive
__device__ unsigned g_ticket;

__device__ __forceinline__ unsigned ld_acq(const unsigned* p) {
    unsigned v;
    asm volatile("ld.global.acquire.gpu.b32 %0, [%1];" : "=r"(v) : "l"(p));
    return v;
}
__device__ __forceinline__ void st_rel(unsigned* p, unsigned v) {
    asm volatile("st.global.release.gpu.b32 [%0], %1;" :: "l"(p), "r"(v));
}

__global__ void k_reset() {
    int i = blockIdx.x * blockDim.x + threadIdx.x;
    if (i < NITEM) g_flag[i] = 0u;
    if (i == 0) g_ticket = 0u;
}

__global__ void __launch_bounds__(TPB, 3)
k_scan(const float* __restrict__ a,
       const float* __restrict__ u,
       const float* __restrict__ x0,
       float* __restrict__ out)
{
    __shared__ unsigned sh_t;
    const int tid  = threadIdx.x;
    const int wid  = tid >> 5;
    const int lane = tid & 31;

    if (tid == 0) sh_t = atomicAdd(&g_ticket, 1u);
    __syncthreads();
    // Item id: 8 consecutive items per ticket; chain = g mod 256 ensures every
    // predecessor (chain, c-1) = g-256 sits in a strictly earlier ticket.
    const int g     = (int)(sh_t * 8u) + wid;
    const int chain = g & (NCHAIN - 1);
    const int c     = g >> 8;
    const int b     = chain >> 5;           // 32 slices per b
    const int sl    = chain & 31;

    const long base = (long)(b * T_ + c * L_) * D_ + sl * SLICE_ + lane;
    const float* __restrict__ ap = a + base;
    const float* __restrict__ up = u + base;

    // ---- Phase 1: load payload into registers (32 independent scalar LDGs)
    float av[L_], uv[L_];
    #pragma unroll
    for (int t = 0; t < L_; ++t) av[t] = ap[(long)t * D_];
    #pragma unroll
    for (int t = 0; t < L_; ++t) uv[t] = up[(long)t * D_];
    if (c == 0)  // fold x0 into u at global t=0
        uv[0] = fmaf(av[0], x0[b * D_ + sl * SLICE_ + lane], uv[0]);

    // Local aggregate: A = prod(a), U = zero-carry scan tail
    float A = av[0], U = uv[0];
    #pragma unroll
    for (int t = 1; t < L_; ++t) {
        U = fmaf(av[t], U, uv[t]);
        A = A * av[t];
    }

    const int si = g * SLICE_ + lane;
    float x_in = 0.f;

    if (c == 0) {
        g_X[si] = U;                         // inclusive known immediately
        __syncwarp();
        if (lane == 0) { __threadfence(); st_rel(&g_flag[g], 2u); }
    } else {
        g_A[si] = A;                         // publish aggregate ASAP
        g_U[si] = U;
        __syncwarp();
        if (lane == 0) { __threadfence(); st_rel(&g_flag[g], 1u); }

        // ---- Phase 2: warp-autonomous batched lookback (LB_W preds / round)
        float As = 1.f, Us = 0.f;
        int p = g - NCHAIN;                  // predecessor item id (same chain)
        for (;;) {
            unsigned f = 0;
            const int pp = p - lane * NCHAIN;
            if (lane < LB_W && pp >= 0) f = ld_acq(&g_flag[pp]);
            const unsigned m1 = __ballot_sync(0xffffffffu, f >= 1u) & 0xFFu;
            const unsigned m2 = __ballot_sync(0xffffffffu, f == 2u) & 0xFFu;
            const unsigned gap = (~m1) & 0xFFu;
            const int navail = gap ? (__ffs(gap) - 1) : LB_W;  // consecutive ready
            const int linc   = m2 ? (__ffs(m2) - 1) : LB_W;    // first inclusive
            int n, inc;
            if (linc < navail) { n = linc; inc = 1; }
            else               { n = navail; inc = 0; }
            if (n == 0 && !inc) continue;    // re-probe at L2 cadence
            __syncwarp();

            float Ab[LB_W], Ub[LB_W], Xv;
            int pi = p * SLICE_ + lane;
            #pragma unroll
            for (int j = 0; j < LB_W; ++j) {
                if (j < n) { Ab[j] = g_A[pi]; Ub[j] = g_U[pi]; }
                pi -= NCHAIN * SLICE_;
            }
            if (inc) Xv = g_X[(p - n * NCHAIN) * SLICE_ + lane];

            #pragma unroll
            for (int j = 0; j < LB_W; ++j) {
                if (j < n) { Us = fmaf(As, Ub[j], Us); As = As * Ab[j]; }
            }
            if (inc) { x_in = fmaf(As, Xv, Us); break; }
            p -= n * NCHAIN;
        }

        // ---- Phase 3: publish inclusive (unblocks successors before output)
        g_X[si] = fmaf(A, x_in, U);
        __syncwarp();
        if (lane == 0) { __threadfence(); st_rel(&g_flag[g], 2u); }
    }

    // ---- Phase 4: replay payload from registers, write outputs
    float* __restrict__ op = out + base;
    float x = x_in;
    #pragma unroll
    for (int t = 0; t < L_; ++t) {
        x = fmaf(av[t], x, uv[t]);
        op[(long)t * D_] = x;
    }
}

extern "C" void kernel_launch(void* const* d_in, const int* in_sizes, int n_in,
                              void* d_out, int out_size) {
    const float* x0 = (const float*)d_in[0];
    const float* a  = (const float*)d_in[1];
    const float* u  = (const float*)d_in[2];
    float* out = (float*)d_out;

    k_reset<<<(NITEM + 255) / 256, 256>>>();
    k_scan<<<NBLK, TPB>>>(a, u, x0, out);
}

// round 8
// speedup vs baseline: 1.7253x; 1.7253x over previous
#include <cuda_runtime.h>

// Shape fixed by the reference
#define B_   8
#define T_   4096
#define D_   1024
#define L_   16                // timesteps per chunk (streamed twice; 2nd hits L2)
#define NC_  (T_ / L_)         // 256 chunks per batch row
#define TPB  256               // 256 thr x float4 = D
#define NBLK (B_ * NC_)        // 2048 blocks
#define LB_W 4                 // lookback batch width

// Decoupled-lookback state (8 MB each -> L2-resident)
__device__ float    g_A[NBLK * D_];   // chunk aggregate: prod(a)
__device__ float    g_U[NBLK * D_];   // chunk aggregate: zero-carry scan tail
__device__ float    g_X[NBLK * D_];   // inclusive state after chunk
__device__ unsigned g_flag[NBLK];     // 0=invalid, 1=aggregate, 2=inclusive
__device__ unsigned g_ticket;

__device__ __forceinline__ float4 f4_fma(float4 a, float4 x, float4 u) {
    float4 r;
    r.x = fmaf(a.x, x.x, u.x); r.y = fmaf(a.y, x.y, u.y);
    r.z = fmaf(a.z, x.z, u.z); r.w = fmaf(a.w, x.w, u.w);
    return r;
}
__device__ __forceinline__ float4 f4_mul(float4 a, float4 b) {
    float4 r; r.x = a.x*b.x; r.y = a.y*b.y; r.z = a.z*b.z; r.w = a.w*b.w; return r;
}
__device__ __forceinline__ unsigned ld_acq(const unsigned* p) {
    unsigned v;
    asm volatile("ld.global.acquire.gpu.b32 %0, [%1];" : "=r"(v) : "l"(p) : "memory");
    return v;
}
__device__ __forceinline__ void st_rel(unsigned* p, unsigned v) {
    asm volatile("st.global.release.gpu.b32 [%0], %1;" :: "l"(p), "r"(v) : "memory");
}
__device__ __forceinline__ void st_stream(float4* p, float4 v) {
    asm volatile("st.global.cs.v4.f32 [%0], {%1,%2,%3,%4};"
                 :: "l"(p), "f"(v.x), "f"(v.y), "f"(v.z), "f"(v.w) : "memory");
}

__global__ void k_reset() {
    int i = blockIdx.x * blockDim.x + threadIdx.x;
    if (i < NBLK) g_flag[i] = 0u;
    if (i == 0) g_ticket = 0u;
}

__global__ void __launch_bounds__(TPB, 2)
k_scan(const float* __restrict__ a,
       const float* __restrict__ u,
       const float* __restrict__ x0,
       float* __restrict__ out)
{
    __shared__ unsigned sh_vid;
    __shared__ int sh_n;
    __shared__ int sh_inc;
    const int tid = threadIdx.x;

    if (tid == 0) sh_vid = atomicAdd(&g_ticket, 1u);
    __syncthreads();
    const unsigned vid = sh_vid;
    const int b = vid & (B_ - 1);      // round-robin b: all 8 chains advance together
    const int c = (int)(vid >> 3);
    const int d = tid * 4;

    const long base = (((long)b * T_ + (long)c * L_) * D_ + d) >> 2;  // float4 units
    const float4* __restrict__ ap = reinterpret_cast<const float4*>(a) + base;
    const float4* __restrict__ up = reinterpret_cast<const float4*>(u) + base;

    // ---- Phase 1: stream chunk, compute aggregate (A = prod a, U = zero-carry scan)
    float4 A, U;
    {
        float4 av0 = ap[0];
        float4 uv0 = up[0];
        if (c == 0) {
            float4 x0v = reinterpret_cast<const float4*>(x0)[(b * D_ + d) >> 2];
            uv0 = f4_fma(av0, x0v, uv0);
        }
        A = av0; U = uv0;
        #pragma unroll 4
        for (int t = 1; t < L_; ++t) {
            float4 av = ap[(long)t * (D_ / 4)];
            float4 uv = up[(long)t * (D_ / 4)];
            U = f4_fma(av, U, uv);
            A = f4_mul(A, av);
        }
    }

    float4* gA4 = reinterpret_cast<float4*>(g_A);
    float4* gU4 = reinterpret_cast<float4*>(g_U);
    float4* gX4 = reinterpret_cast<float4*>(g_X);
    const int si = ((b * NC_ + c) * D_ + d) >> 2;

    float4 x_in = make_float4(0.f, 0.f, 0.f, 0.f);

    if (c == 0) {
        gX4[si] = U;                       // inclusive known immediately
        __syncthreads();                   // all block stores done before release
        if (tid == 0) st_rel(&g_flag[b * NC_], 2u);
    } else {
        // publish aggregate ASAP
        gA4[si] = A;
        gU4[si] = U;
        __syncthreads();
        if (tid == 0) st_rel(&g_flag[b * NC_ + c], 1u);

        // ---- Phase 2: batched decoupled lookback (LB_W predecessors per round)
        float4 As = make_float4(1.f, 1.f, 1.f, 1.f);
        float4 Us = make_float4(0.f, 0.f, 0.f, 0.f);
        int p = c - 1;
        for (;;) {
            if (tid < 32) {                 // one flag round-trip covers LB_W preds
                const int lane = tid;
                const int pp = p - lane;
                unsigned f = 0;
                if (lane < LB_W && pp >= 0) f = ld_acq(&g_flag[b * NC_ + pp]);
                unsigned m1 = __ballot_sync(0xffffffffu, f >= 1u) & ((1u << LB_W) - 1u);
                unsigned m2 = __ballot_sync(0xffffffffu, f == 2u) & ((1u << LB_W) - 1u);
                if (lane == 0) {
                    unsigned gap = (~m1) & ((1u << LB_W) - 1u);
                    int navail = gap ? (__ffs(gap) - 1) : LB_W;   // consecutive published
                    int linc   = m2 ? (__ffs(m2) - 1) : LB_W;     // first inclusive slot
                    if (linc < navail) { sh_n = linc; sh_inc = 1; }
                    else               { sh_n = navail; sh_inc = 0; }
                }
            }
            __syncthreads();
            const int n   = sh_n;
            const int inc = sh_inc;
            __syncthreads();                // smem reusable next round

            if (n == 0 && !inc) { __nanosleep(128); continue; }

            // batched aggregate loads (up to 8 concurrent float4 loads + X)
            float4 Ap0, Up0, Ap1, Up1, Ap2, Up2, Ap3, Up3, Xv;
            int pi = ((b * NC_ + p) * D_ + d) >> 2;
            if (0 < n) { Ap0 = gA4[pi]; Up0 = gU4[pi]; }  pi -= D_ / 4;
            if (1 < n) { Ap1 = gA4[pi]; Up1 = gU4[pi]; }  pi -= D_ / 4;
            if (2 < n) { Ap2 = gA4[pi]; Up2 = gU4[pi]; }  pi -= D_ / 4;
            if (3 < n) { Ap3 = gA4[pi]; Up3 = gU4[pi]; }
            if (inc) Xv = gX4[((b * NC_ + (p - n)) * D_ + d) >> 2];

            if (0 < n) { Us = f4_fma(As, Up0, Us); As = f4_mul(As, Ap0); }
            if (1 < n) { Us = f4_fma(As, Up1, Us); As = f4_mul(As, Ap1); }
            if (2 < n) { Us = f4_fma(As, Up2, Us); As = f4_mul(As, Ap2); }
            if (3 < n) { Us = f4_fma(As, Up3, Us); As = f4_mul(As, Ap3); }
            if (inc) { x_in = f4_fma(As, Xv, Us); break; }
            p -= n;
        }

        // ---- Phase 3: publish inclusive (unblocks successors before phase 4)
        gX4[si] = f4_fma(A, x_in, U);
        __syncthreads();
        if (tid == 0) st_rel(&g_flag[b * NC_ + c], 2u);
    }

    // ---- Phase 4: re-stream chunk (L2-warm at this occupancy) and write outputs
    float4* __restrict__ op = reinterpret_cast<float4*>(out) + base;
    float4 x = x_in;
    float4 x0v;
    if (c == 0) x0v = reinterpret_cast<const float4*>(x0)[(b * D_ + d) >> 2];
    #pragma unroll 4
    for (int t = 0; t < L_; ++t) {
        float4 av = ap[(long)t * (D_ / 4)];
        float4 uv = up[(long)t * (D_ / 4)];
        if (c == 0 && t == 0) uv = f4_fma(av, x0v, uv);
        x = f4_fma(av, x, uv);
        st_stream(op + (long)t * (D_ / 4), x);   // evict-first: protect a,u window
    }
}

extern "C" void kernel_launch(void* const* d_in, const int* in_sizes, int n_in,
                              void* d_out, int out_size) {
    const float* x0 = (const float*)d_in[0];
    const float* a  = (const float*)d_in[1];
    const float* u  = (const float*)d_in[2];
    float* out = (float*)d_out;

    k_reset<<<(NBLK + 255) / 256, 256>>>();
    k_scan<<<NBLK, TPB>>>(a, u, x0, out);
}